// round 5
// baseline (speedup 1.0000x reference)
#include <cuda_runtime.h>
#include <stdint.h>

#define NB     8
#define NF4    65536              // float4 groups per sample
#define NBINS  2048
#define GRID   592                // 4 blocks/SM * 148
#define BPS    74                 // blocks per sample
#define STRIDE (BPS * 256)
#define ITER   4
#define MARGIN 5000               // ~10 sigma of 4x-subsample count noise

__device__ uint4    g_pk   [NB * NF4];      // 8MB packed bf16x2 scratch
__device__ unsigned g_hist1[2][NB][NBINS];  // subsampled level-1 histogram
__device__ unsigned g_win  [2][NB][NBINS];  // window counts (code- or bin-granularity)
__device__ float    g_wsum [2][NB][NBINS];  // window sums (bin-mode only)
__device__ unsigned g_cntU [2][NB];         // exact unknown count (dup per array)
__device__ float    g_Sab  [2][NB];         // exact sum above window
__device__ unsigned g_Cab  [2][NB];         // exact count above window
__device__ int      g_wlo  [2][NB];
__device__ int      g_whi  [2][NB];
__device__ unsigned g_bar  [8];             // monotonic epoch counters (never reset)

__device__ __forceinline__ unsigned f2bf(float f) {   // RNE f32->bf16 bits (nonneg finite)
    unsigned u = __float_as_uint(f);
    return (u + 0x7FFFu + ((u >> 16) & 1u)) >> 16;
}
__device__ __forceinline__ float bf2f(unsigned b) { return __uint_as_float(b << 16); }
__device__ __forceinline__ float pget(const float4& v, int p) { return p == 0 ? v.x : p == 1 ? v.y : p == 2 ? v.z : v.w; }
__device__ __forceinline__ int   tget(const int4&   v, int p) { return p == 0 ? v.x : p == 1 ? v.y : p == 2 ? v.z : v.w; }

__device__ __forceinline__ void grid_barrier(int id) {
    __syncthreads();
    if (threadIdx.x == 0) {
        __threadfence();
        unsigned old = atomicAdd(&g_bar[id], 1u);
        unsigned target = old - (old % GRID) + GRID;
        while (*((volatile unsigned*)&g_bar[id]) < target) __nanosleep(64);
        __threadfence();
    }
    __syncthreads();
}

__global__ void __launch_bounds__(256, 4)
kFused(const float4* __restrict__ img, const float4* __restrict__ alp,
       const float4* __restrict__ prd, const int4*   __restrict__ tri,
       const float4* __restrict__ fg,  const float4* __restrict__ bg,
       float* out)
{
    __shared__ unsigned sh[2][NBINS];        // 16KB, reused per phase
    __shared__ unsigned wt[8];
    __shared__ float    wtf[8];
    __shared__ unsigned s_ru[8];
    __shared__ float    s_rf0[8], s_rf1[8];
    __shared__ unsigned s_rc0[8], s_rc1[8];
    __shared__ int      s_par[4];

    const int t   = threadIdx.x;
    const int l   = t & 31, w = t >> 5;
    const int blk = blockIdx.x;
    const int b   = blk / BPS;
    const int lb  = blk - b * BPS;
    const int cb  = b * 3 * NF4;

    for (int i = t; i < 2 * NBINS; i += 256) ((unsigned*)sh)[i] = 0u;
    if (blk == 0 && t == 0) out[0] = 0.0f;
    __syncthreads();

    // ================= PASS A: compute, pack, store; subsampled histogram ===
    unsigned cnt = 0;
    const float inv255 = 1.0f / 255.0f;
#pragma unroll
    for (int j = 0; j < ITER; j++) {
        int gl = lb * 256 + t + j * STRIDE;
        if (gl >= NF4) break;
        int g = b * NF4 + gl;
        int4   tv = tri[g];
        float4 av = alp[g], pv = prd[g];
        float4 i0 = img[cb + gl], i1 = img[cb + NF4 + gl], i2 = img[cb + 2 * NF4 + gl];
        float4 f0 = fg [cb + gl], f1 = fg [cb + NF4 + gl], f2 = fg [cb + 2 * NF4 + gl];
        float4 g0 = bg [cb + gl], g1 = bg [cb + NF4 + gl], g2 = bg [cb + 2 * NF4 + gl];
        unsigned pk[4];
        bool u0 = false;
#pragma unroll
        for (int p = 0; p < 4; p++) {
            bool u = (tget(tv, p) == 128);
            float pr = pget(pv, p), q = 1.0f - pr;
            float d = 0.0f, dc = 0.0f;
            if (u) {
                d  = fabsf(pget(av, p) * inv255 - pr);
                dc = fabsf(pget(i0, p) - (pget(f0, p) * pr + q * pget(g0, p)))
                   + fabsf(pget(i1, p) - (pget(f1, p) * pr + q * pget(g1, p)))
                   + fabsf(pget(i2, p) - (pget(f2, p) * pr + q * pget(g2, p)));
                cnt++;
            }
            if (p == 0) u0 = u;
            pk[p] = f2bf(d) | (f2bf(dc) << 16);
        }
        // subsample histogram: pixel 0 of each float4 (every 4th pixel, unbiased)
        {
            unsigned kd0 = pk[0] & 0xFFFFu, kc0 = pk[0] >> 16;
            int bd = u0 ? (int)(kd0 >> 5) : -1;
            unsigned m1 = __match_any_sync(0xffffffffu, bd);
            if (u0 && (int)(__ffs(m1) - 1) == l) atomicAdd(&sh[0][bd], (unsigned)__popc(m1));
            int bc = u0 ? (int)(kc0 >> 5) : -1;
            unsigned m2 = __match_any_sync(0xffffffffu, bc);
            if (u0 && (int)(__ffs(m2) - 1) == l) atomicAdd(&sh[1][bc], (unsigned)__popc(m2));
        }
        g_pk[g] = make_uint4(pk[0], pk[1], pk[2], pk[3]);
    }
    // exact unknown count (no per-pixel atomics)
    for (int o = 16; o; o >>= 1) cnt += __shfl_down_sync(0xffffffffu, cnt, o);
    if (l == 0) s_ru[w] = cnt;
    __syncthreads();
    if (t == 0) {
        unsigned tot = 0;
#pragma unroll
        for (int i = 0; i < 8; i++) tot += s_ru[i];
        atomicAdd(&g_cntU[0][b], tot);
        atomicAdd(&g_cntU[1][b], tot);
    }
    for (int i = t; i < NBINS; i += 256) {
        unsigned c0 = sh[0][i]; if (c0) atomicAdd(&g_hist1[0][b][i], c0);
        unsigned c1 = sh[1][i]; if (c1) atomicAdd(&g_hist1[1][b][i], c1);
    }

    grid_barrier(0);

    // ================= SELECT: 16 blocks find conservative window ===========
    if (blk < 16) {
        int a = blk >> 3, bb = blk & 7;
        unsigned count = g_cntU[a][bb];
        int k = (int)floorf((float)count * 0.7f);
        if (k <= 0) {
            if (t == 0) { g_wlo[a][bb] = 0; g_whi[a][bb] = -1; }
        } else {
            for (int i = t; i < NBINS; i += 256) sh[0][i] = g_hist1[a][bb][i];
            __syncthreads();
            unsigned loc = 0;
#pragma unroll
            for (int jj = 0; jj < 8; jj++) loc += sh[0][t * 8 + jj];
            unsigned s = loc;
#pragma unroll
            for (int o = 1; o < 32; o <<= 1) {
                unsigned v = __shfl_down_sync(0xffffffffu, s, o);
                if (l + o < 32) s += v;
            }
            if (l == 0) wt[w] = s;
            __syncthreads();
            unsigned wsuf = 0;
            for (int w2 = w + 1; w2 < 8; w2++) wsuf += wt[w2];
            int acc = (int)(wsuf + (s - loc));      // count strictly above bin t*8+7
            int tLo = k + MARGIN;                   // bLo = min{i: 4*cum(i) < tLo}
            int tHi = max(k - MARGIN, 1);           // bHi = min{i: 4*cum(i) < tHi}
#pragma unroll
            for (int jj = 7; jj >= 0; jj--) {
                int i = t * 8 + jj;
                int c = (int)sh[0][i];
                int above  = 4 * acc;               // est count above bin i
                int aboveP = 4 * (acc + c);         // est count above bin i-1
                if (above < tLo && (i == 0 || aboveP >= tLo)) g_wlo[a][bb] = i;
                if (above < tHi && (i == 0 || aboveP >= tHi)) g_whi[a][bb] = i;
                acc += c;
            }
        }
    }

    grid_barrier(1);

    // ================= PASS B: exact above-window sums + window histogram ===
    if (t == 0) {
        s_par[0] = g_wlo[0][b]; s_par[1] = g_whi[0][b];
        s_par[2] = g_wlo[1][b]; s_par[3] = g_whi[1][b];
    }
    __syncthreads();
    const int wloD = s_par[0], whiD = s_par[1], wloC = s_par[2], whiC = s_par[3];
    const unsigned aboveD = (unsigned)((whiD + 1) << 5);
    const unsigned loD    = (unsigned)(wloD << 5);
    const bool     cmD    = (whiD - wloD) <= 63;    // code-granularity mode
    const unsigned aboveC = (unsigned)((whiC + 1) << 5);
    const unsigned loC    = (unsigned)(wloC << 5);
    const bool     cmC    = (whiC - wloC) <= 63;

    float s0 = 0.0f, s1 = 0.0f;
    unsigned c0 = 0, c1 = 0;
#pragma unroll
    for (int j = 0; j < ITER; j++) {
        int gl = lb * 256 + t + j * STRIDE;
        if (gl >= NF4) break;
        uint4 pv4 = g_pk[b * NF4 + gl];
        unsigned pk4[4] = { pv4.x, pv4.y, pv4.z, pv4.w };
#pragma unroll
        for (int p = 0; p < 4; p++) {
            unsigned kd = pk4[p] & 0xFFFFu, kc = pk4[p] >> 16;
            if (kd >= aboveD) { s0 += bf2f(kd); c0++; }
            else if (kd >= loD) {
                int idx = cmD ? (int)(kd - loD) : (int)(kd >> 5) - wloD;
                atomicAdd(&g_win[0][b][idx], 1u);
                if (!cmD) atomicAdd(&g_wsum[0][b][idx], bf2f(kd));
            }
            if (kc >= aboveC) { s1 += bf2f(kc); c1++; }
            else if (kc >= loC) {
                int idx = cmC ? (int)(kc - loC) : (int)(kc >> 5) - wloC;
                atomicAdd(&g_win[1][b][idx], 1u);
                if (!cmC) atomicAdd(&g_wsum[1][b][idx], bf2f(kc));
            }
        }
    }
    for (int o = 16; o; o >>= 1) {
        s0 += __shfl_down_sync(0xffffffffu, s0, o);
        s1 += __shfl_down_sync(0xffffffffu, s1, o);
        c0 += __shfl_down_sync(0xffffffffu, c0, o);
        c1 += __shfl_down_sync(0xffffffffu, c1, o);
    }
    if (l == 0) { s_rf0[w] = s0; s_rf1[w] = s1; s_rc0[w] = c0; s_rc1[w] = c1; }
    __syncthreads();
    if (t == 0) {
        float a0 = 0.f, a1 = 0.f; unsigned b0 = 0, b1 = 0;
#pragma unroll
        for (int i = 0; i < 8; i++) { a0 += s_rf0[i]; a1 += s_rf1[i]; b0 += s_rc0[i]; b1 += s_rc1[i]; }
        atomicAdd(&g_Sab[0][b], a0);  atomicAdd(&g_Sab[1][b], a1);
        atomicAdd(&g_Cab[0][b], b0);  atomicAdd(&g_Cab[1][b], b1);
    }

    grid_barrier(2);

    // ================= FINALIZE (16 blocks) + cleanup (others) ==============
    if (blk >= 16) {
        int gid = (blk - 16) * 256 + t;
        if (gid < 2 * NB * NBINS) ((unsigned*)g_hist1)[gid] = 0u;
    } else {
        int a = blk >> 3, bb = blk & 7;
        unsigned count = g_cntU[a][bb];
        int k = (int)floorf((float)count * 0.7f);
        int wlo = g_wlo[a][bb], whi = g_whi[a][bb];
        bool cm = (whi - wlo) <= 63;
        unsigned loKey = (unsigned)(wlo << 5);
        if (k > 0) {
            for (int i = t; i < NBINS; i += 256) {
                unsigned c = g_win[a][bb][i];
                sh[0][i] = c;
                float v = cm ? (float)c * bf2f(loKey + (unsigned)i) : g_wsum[a][bb][i];
                ((float*)sh[1])[i] = v;
            }
            __syncthreads();
            unsigned lc = 0; float lv = 0.f;
#pragma unroll
            for (int jj = 0; jj < 8; jj++) { lc += sh[0][t * 8 + jj]; lv += ((float*)sh[1])[t * 8 + jj]; }
            unsigned sc = lc; float sv = lv;
#pragma unroll
            for (int o = 1; o < 32; o <<= 1) {
                unsigned vc = __shfl_down_sync(0xffffffffu, sc, o);
                float    vv = __shfl_down_sync(0xffffffffu, sv, o);
                if (l + o < 32) { sc += vc; sv += vv; }
            }
            if (l == 0) { wt[w] = sc; wtf[w] = sv; }
            __syncthreads();
            unsigned wsufC = 0; float wsufS = 0.f;
            for (int w2 = w + 1; w2 < 8; w2++) { wsufC += wt[w2]; wsufS += wtf[w2]; }
            unsigned acc  = wsufC + (sc - lc);
            float    accS = wsufS + (sv - lv);
            unsigned Cab = g_Cab[a][bb];
            float    Sab = g_Sab[a][bb];
#pragma unroll
            for (int jj = 7; jj >= 0; jj--) {
                int i = t * 8 + jj;
                unsigned c = sh[0][i];
                unsigned ta = Cab + acc;                       // exact count above entry i
                if (c > 0 && ta < (unsigned)k && ta + c >= (unsigned)k) {
                    float val = ((float*)sh[1])[i];
                    float mean = val / (float)c;               // code mode: exact code value
                    float S = Sab + accS + (float)((unsigned)k - ta) * mean;
                    atomicAdd(out, 0.0625f * (S / ((float)k + 1e-6f)));
                }
                acc += c; accS += ((float*)sh[1])[i];
            }
            __syncthreads();
        }
        // per-unit-owned cleanup (no extra barrier needed)
        for (int i = t; i < NBINS; i += 256) { g_win[a][bb][i] = 0u; g_wsum[a][bb][i] = 0.f; }
        if (t == 0) { g_cntU[a][bb] = 0u; g_Sab[a][bb] = 0.f; g_Cab[a][bb] = 0u; }
    }
}

extern "C" void kernel_launch(void* const* d_in, const int* in_sizes, int n_in,
                              void* d_out, int out_size) {
    const float4* img = (const float4*)d_in[0];
    const float4* alp = (const float4*)d_in[1];
    const float4* prd = (const float4*)d_in[2];
    const int4*   tri = (const int4*)  d_in[3];
    const float4* fg  = (const float4*)d_in[4];
    const float4* bg  = (const float4*)d_in[5];
    kFused<<<GRID, 256>>>(img, alp, prd, tri, fg, bg, (float*)d_out);
}